// round 7
// baseline (speedup 1.0000x reference)
#include <cuda_runtime.h>
#include <cuda_bf16.h>
#include <cstdint>
#include <math.h>

// Problem constants
#define B_    16
#define N_    2048
#define D_    128
#define H_    8
#define F_    65
#define ROWS_ 32768
#define N1_   3120       // q,k,v * 8 heads * 130 (re/im interleaved: u = 2f+p)
#define N1P_  3200       // 25 n-tiles of 128
#define NK_   1040
#define NKP_  1152       // 9*128
#define SCALE_ (1.0f/65.0f)
#define EQ_   8          // att e-chunks

// ---------------- scratch (static device, no allocation) ----------------
__device__ __nv_bfloat16 g_Xhi[(size_t)ROWS_ * D_];
__device__ __nv_bfloat16 g_Xlo[(size_t)ROWS_ * D_];
__device__ __nv_bfloat16 g_W1T_hi[N1P_ * D_];    // [3200][128]
__device__ __nv_bfloat16 g_W1T_lo[N1P_ * D_];
__device__ float g_Mout[H_ * 2 * F_ * D_];       // [h][p][x][o]
__device__ float g_aq[(size_t)ROWS_ * H_ * F_];
__device__ float g_ak[(size_t)ROWS_ * H_ * F_];
__device__ float g_attp[B_ * H_ * EQ_ * F_ * F_];
__device__ float g_att[B_ * H_ * F_ * F_];
__device__ __nv_bfloat16 g_Vhi[(size_t)ROWS_ * NKP_]; // pads stay 0
__device__ __nv_bfloat16 g_Vlo[(size_t)ROWS_ * NKP_];
__device__ __nv_bfloat16 g_CThi[B_ * D_ * NKP_];
__device__ __nv_bfloat16 g_CTlo[B_ * D_ * NKP_];

// ---------------- helpers ----------------
__device__ __forceinline__ uint32_t smem_u32(const void* p) {
    uint32_t a;
    asm("{ .reg .u64 t; cvta.to.shared.u64 t, %1; cvt.u32.u64 %0, t; }" : "=r"(a) : "l"(p));
    return a;
}
__device__ __forceinline__ void ldsm_x4(uint32_t* r, uint32_t addr) {
    asm volatile("ldmatrix.sync.aligned.m8n8.x4.shared.b16 {%0,%1,%2,%3}, [%4];"
                 : "=r"(r[0]), "=r"(r[1]), "=r"(r[2]), "=r"(r[3]) : "r"(addr));
}
__device__ __forceinline__ void mma16816(float* c, const uint32_t* a, const uint32_t* b) {
    asm volatile("mma.sync.aligned.m16n8k16.row.col.f32.bf16.bf16.f32 "
                 "{%0,%1,%2,%3}, {%4,%5,%6,%7}, {%8,%9}, {%0,%1,%2,%3};"
                 : "+f"(c[0]), "+f"(c[1]), "+f"(c[2]), "+f"(c[3])
                 : "r"(a[0]), "r"(a[1]), "r"(a[2]), "r"(a[3]), "r"(b[0]), "r"(b[1]));
}
__device__ __forceinline__ uint32_t pack_bf(__nv_bfloat16 a, __nv_bfloat16 b) {
    __nv_bfloat162 p = __halves2bfloat162(a, b);
    return *reinterpret_cast<uint32_t*>(&p);
}
// swizzled offset within a [rows][64 bf16] tile (row = 128 bytes)
__device__ __forceinline__ uint32_t swz64(int row, int colbyte) {
    return (uint32_t)(row * 128 + (colbyte ^ ((row & 7) << 4)));
}
__device__ __forceinline__ void cp16(uint32_t dst, const void* src) {
    asm volatile("cp.async.cg.shared.global [%0], [%1], 16;" :: "r"(dst), "l"(src));
}
__device__ __forceinline__ void cp_commit() { asm volatile("cp.async.commit_group;"); }
__device__ __forceinline__ void cp_wait1() { asm volatile("cp.async.wait_group 1;" ::: "memory"); }
__device__ __forceinline__ void cp_wait2() { asm volatile("cp.async.wait_group 2;" ::: "memory"); }

// 3-pass mma sweep over one resident [*x64] K-chunk (4 k-steps), warp grid 4x2
__device__ __forceinline__ void mma_chunk64(uint32_t sAhi, uint32_t sAlo,
                                            uint32_t sBhi, uint32_t sBlo,
                                            int lane, int wm, int wn, float c[2][8][4]) {
    #pragma unroll
    for (int p = 0; p < 3; p++) {
        uint32_t sA = (p == 2) ? sAlo : sAhi;
        uint32_t sB = (p == 1) ? sBlo : sBhi;
        #pragma unroll
        for (int ks = 0; ks < 4; ks++) {
            int colb = ks * 32 + (lane >> 4) * 16;
            uint32_t a[2][4];
            #pragma unroll
            for (int tm = 0; tm < 2; tm++) {
                int r = wm * 32 + tm * 16 + (lane & 15);
                ldsm_x4(a[tm], sA + swz64(r, colb));
            }
            uint32_t b[8][2];
            #pragma unroll
            for (int ng = 0; ng < 4; ng++) {
                int n = wn * 64 + ng * 16 + (lane & 15);
                uint32_t q[4];
                ldsm_x4(q, sB + swz64(n, colb));
                b[2 * ng][0] = q[0]; b[2 * ng + 1][0] = q[1];
                b[2 * ng][1] = q[2]; b[2 * ng + 1][1] = q[3];
            }
            #pragma unroll
            for (int tm = 0; tm < 2; tm++)
                #pragma unroll
                for (int tn = 0; tn < 8; tn++)
                    mma16816(c[tm][tn], a[tm], b[tn]);
        }
    }
}

// ---------------- X pre-split ----------------
__global__ void split_x_kernel(const float* __restrict__ X) {
    size_t i = (size_t)blockIdx.x * blockDim.x + threadIdx.x;
    float4 v = ((const float4*)X)[i];
    __nv_bfloat16 h0 = __float2bfloat16(v.x), h1 = __float2bfloat16(v.y);
    __nv_bfloat16 h2 = __float2bfloat16(v.z), h3 = __float2bfloat16(v.w);
    ((uint2*)g_Xhi)[i] = make_uint2(pack_bf(h0, h1), pack_bf(h2, h3));
    ((uint2*)g_Xlo)[i] = make_uint2(
        pack_bf(__float2bfloat16(v.x - __bfloat162float(h0)),
                __float2bfloat16(v.y - __bfloat162float(h1))),
        pack_bf(__float2bfloat16(v.z - __bfloat162float(h2)),
                __float2bfloat16(v.w - __bfloat162float(h3))));
}

// ---------------- weight folding ----------------
__global__ void build_w1_kernel(const float* __restrict__ w_qkv) {
    __shared__ float cs[128], sn[128];
    int t = threadIdx.x;
    if (t < 128) {
        float ang = (float)t / 64.0f;
        cs[t] = cospif(ang);
        sn[t] = sinpif(ang);
    }
    __syncthreads();
    const int total = N1P_ * D_;
    for (int idx = blockIdx.x * blockDim.x + t; idx < total; idx += gridDim.x * blockDim.x) {
        int c = idx >> 7, d = idx & 127;
        float acc = 0.f;
        if (c < N1_) {
            int region = c / 1040;
            int cc = c - region * 1040;
            int hd = cc / 130;
            int u = cc - hd * 130;
            int f = u >> 1;
            const float* w = w_qkv + (size_t)d * 3072 + region * 1024 + hd * 128;
            if ((u & 1) == 0) {
                #pragma unroll 8
                for (int dd = 0; dd < 128; dd++) acc += w[dd] * cs[(f * dd) & 127];
            } else {
                #pragma unroll 8
                for (int dd = 0; dd < 128; dd++) acc -= w[dd] * sn[(f * dd) & 127];
            }
            if (region != 2) acc *= SCALE_;
        }
        __nv_bfloat16 hi = __float2bfloat16(acc);
        g_W1T_hi[idx] = hi;
        g_W1T_lo[idx] = __float2bfloat16(acc - __bfloat162float(hi));
    }
}

__global__ void build_mout_kernel(const float* __restrict__ w_out) {
    __shared__ float cs[128], sn[128];
    int t = threadIdx.x;
    if (t < 128) {
        float ang = (float)t / 64.0f;
        cs[t] = cospif(ang);
        sn[t] = sinpif(ang);
    }
    __syncthreads();
    const int total = H_ * 2 * F_ * D_;
    for (int idx = blockIdx.x * blockDim.x + t; idx < total; idx += gridDim.x * blockDim.x) {
        int o = idx & 127;
        int r = idx >> 7;
        int x = r % 65;
        int hp = r / 65;
        int p = hp & 1, hd = hp >> 1;
        float acc = 0.f;
        if (p == 0) {
            #pragma unroll 8
            for (int t2 = 0; t2 < 128; t2++)
                acc += cs[(x * t2) & 127] * w_out[(size_t)(hd * 128 + t2) * 128 + o];
            acc *= ((x == 0 || x == 64) ? 1.0f : 2.0f) / 128.0f;
        } else if (x != 0 && x != 64) {
            #pragma unroll 8
            for (int t2 = 0; t2 < 128; t2++)
                acc -= sn[(x * t2) & 127] * w_out[(size_t)(hd * 128 + t2) * 128 + o];
            acc *= 2.0f / 128.0f;
        }
        g_Mout[idx] = acc;
    }
}

// ---------------- GEMM1: A-stationary n-loop ----------------
// SMEM: A hi 2x16K @0, A lo @32768; B stages (64KB each: hi c0,c1 / lo c0,c1) @65536
#define G1_B0   65536
#define G1_BSTG 65536
#define G1_TOT  (65536 + 2 * G1_BSTG)   // 192KB

__device__ __forceinline__ void g1_load_a(uint32_t sb, int bm, int tid) {
    for (int u = tid; u < 2048; u += 256) {
        int r = u >> 4, seg = u & 15;
        int chunk = seg >> 3, cbl = (seg & 7) * 16;
        uint32_t d = chunk * 16384 + swz64(r, cbl);
        size_t src = (size_t)(bm + r) * 256 + chunk * 128 + cbl;   // bytes
        cp16(sb + d,         (const char*)g_Xhi + src);
        cp16(sb + 32768 + d, (const char*)g_Xlo + src);
    }
}
__device__ __forceinline__ void g1_load_b(uint32_t bs, int nt, int tid) {
    int bn = nt * 128;
    for (int u = tid; u < 2048; u += 256) {
        int r = u >> 4, seg = u & 15;
        int chunk = seg >> 3, cbl = (seg & 7) * 16;
        uint32_t d = chunk * 16384 + swz64(r, cbl);
        size_t src = (size_t)(bn + r) * 256 + chunk * 128 + cbl;
        cp16(bs + d,         (const char*)g_W1T_hi + src);
        cp16(bs + 32768 + d, (const char*)g_W1T_lo + src);
    }
}

__global__ void __launch_bounds__(256, 1) gemm1_tc() {
    extern __shared__ char smem[];
    uint32_t sb = smem_u32(smem);
    int tid = threadIdx.x;
    int lane = tid & 31, wid = tid >> 5;
    int wm = wid & 3, wn = wid >> 2;         // 4 x 2 warps over 128 x 128
    int bm = blockIdx.x * 128;
    int grp = blockIdx.y;                     // 0: tiles 0..12, 1: tiles 13..24
    int t0 = grp * 13;
    int ntiles = grp ? 12 : 13;

    g1_load_a(sb, bm, tid);  cp_commit();
    g1_load_b(sb + G1_B0, t0, tid);  cp_commit();
    g1_load_b(sb + G1_B0 + G1_BSTG, t0 + 1, tid);  cp_commit();

    int g = lane >> 2, cp2 = (lane & 3) * 2;

    for (int it = 0; it < ntiles; it++) {
        float c[2][8][4];
        #pragma unroll
        for (int i = 0; i < 2; i++)
            #pragma unroll
            for (int j = 0; j < 8; j++)
                #pragma unroll
                for (int k = 0; k < 4; k++) c[i][j][k] = 0.f;

        cp_wait1();
        __syncthreads();
        uint32_t bs = sb + G1_B0 + (it & 1) * G1_BSTG;
        #pragma unroll
        for (int ch = 0; ch < 2; ch++)
            mma_chunk64(sb + ch * 16384, sb + 32768 + ch * 16384,
                        bs + ch * 16384, bs + 32768 + ch * 16384,
                        lane, wm, wn, c);
        __syncthreads();
        if (it + 2 < ntiles) { g1_load_b(bs, t0 + it + 2, tid); cp_commit(); }

        // epilogue for n-tile t0+it (overlaps with the async B load)
        int bn = (t0 + it) * 128;
        #pragma unroll
        for (int tn = 0; tn < 8; tn++) {
            int col = bn + wn * 64 + tn * 8 + cp2;   // even
            if (col >= N1_) continue;
            int region = col / 1040;
            int cc = col - region * 1040;
            int hd = cc / 130;
            int uu = cc - hd * 130;
            int f = uu >> 1;
            #pragma unroll
            for (int tm = 0; tm < 2; tm++)
                #pragma unroll
                for (int hf = 0; hf < 2; hf++) {
                    size_t row = (size_t)bm + wm * 32 + tm * 16 + hf * 8 + g;
                    float re = c[tm][tn][hf * 2], im = c[tm][tn][hf * 2 + 1];
                    if (region == 0) {
                        g_aq[(row * 8 + hd) * 65 + f] = sqrtf(re * re + im * im);
                    } else if (region == 1) {
                        g_ak[(row * 8 + hd) * 65 + f] = sqrtf(re * re + im * im);
                    } else {
                        __nv_bfloat16 rh = __float2bfloat16(re), ih = __float2bfloat16(im);
                        __nv_bfloat16 rl = __float2bfloat16(re - __bfloat162float(rh));
                        __nv_bfloat16 il = __float2bfloat16(im - __bfloat162float(ih));
                        size_t off = (row * NKP_ + cc) * 2;
                        *(uint32_t*)((char*)g_Vhi + off) = pack_bf(rh, ih);
                        *(uint32_t*)((char*)g_Vlo + off) = pack_bf(rl, il);
                    }
                }
        }
    }
}

// ---------------- att partial: [f][e] transposed smem, float4 over e ----------------
__global__ void __launch_bounds__(256) att_partial_kernel() {
    __shared__ float aqs[65 * 68];
    __shared__ float aks[65 * 68];
    int bh = blockIdx.y;
    int b = bh >> 3, h = bh & 7;
    int chunk = blockIdx.x;
    int tid = threadIdx.x;
    int tx = tid & 15, ty = tid >> 4;
    int xs[5], ys[5];
    #pragma unroll
    for (int i = 0; i < 5; i++) {
        int x = tx + 16 * i; xs[i] = (x < 65) ? x : 0;
        int y = ty + 16 * i; ys[i] = (y < 65) ? y : 0;
    }
    float acc[5][5];
    #pragma unroll
    for (int i = 0; i < 5; i++)
        #pragma unroll
        for (int j = 0; j < 5; j++) acc[i][j] = 0.f;

    int ebase = chunk * (2048 / EQ_);
    for (int e0 = ebase; e0 < ebase + 2048 / EQ_; e0 += 64) {
        for (int idx = tid; idx < 4160; idx += 256) {
            int r = idx / 65, f = idx - r * 65;
            size_t gidx = ((size_t)((b * 2048 + e0 + r) * 8 + h)) * 65 + f;
            aqs[f * 68 + r] = g_aq[gidx];
            aks[f * 68 + r] = g_ak[gidx];
        }
        __syncthreads();
        #pragma unroll 2
        for (int e4 = 0; e4 < 64; e4 += 4) {
            float4 av[5], bv[5];
            #pragma unroll
            for (int i = 0; i < 5; i++) av[i] = *(const float4*)&aqs[xs[i] * 68 + e4];
            #pragma unroll
            for (int j = 0; j < 5; j++) bv[j] = *(const float4*)&aks[ys[j] * 68 + e4];
            #pragma unroll
            for (int i = 0; i < 5; i++)
                #pragma unroll
                for (int j = 0; j < 5; j++) {
                    acc[i][j] += av[i].x * bv[j].x;
                    acc[i][j] += av[i].y * bv[j].y;
                    acc[i][j] += av[i].z * bv[j].z;
                    acc[i][j] += av[i].w * bv[j].w;
                }
        }
        __syncthreads();
    }
    float* dst = g_attp + (size_t)(bh * EQ_ + chunk) * 4225;
    #pragma unroll
    for (int i = 0; i < 5; i++) {
        int x = tx + 16 * i;
        if (x < 65)
            #pragma unroll
            for (int j = 0; j < 5; j++) {
                int y = ty + 16 * j;
                if (y < 65) dst[x * 65 + y] = acc[i][j];
            }
    }
}

// ---------------- softmax ----------------
__global__ void __launch_bounds__(256) att_softmax_kernel() {
    __shared__ float sm[4225];
    int bh = blockIdx.x;
    int tid = threadIdx.x;
    const float* p0 = g_attp + (size_t)(bh * EQ_) * 4225;
    for (int idx = tid; idx < 4225; idx += 256) {
        float s = 0.f;
        #pragma unroll
        for (int q = 0; q < EQ_; q++) s += p0[q * 4225 + idx];
        sm[idx] = s;
    }
    __syncthreads();
    int warp = tid >> 5, lane = tid & 31;
    for (int x = warp; x < 65; x += 8) {
        float m = -3.4e38f;
        for (int y = lane; y < 65; y += 32) m = fmaxf(m, sm[x * 65 + y]);
        #pragma unroll
        for (int o = 16; o; o >>= 1) m = fmaxf(m, __shfl_xor_sync(0xffffffffu, m, o));
        float s = 0.f;
        for (int y = lane; y < 65; y += 32) {
            float v = expf(sm[x * 65 + y] - m);
            sm[x * 65 + y] = v;
            s += v;
        }
        #pragma unroll
        for (int o = 16; o; o >>= 1) s += __shfl_xor_sync(0xffffffffu, s, o);
        float inv = 1.0f / s;
        for (int y = lane; y < 65; y += 32)
            g_att[(size_t)bh * 4225 + x * 65 + y] = sm[x * 65 + y] * inv;
    }
}

// ---------------- build C_b ----------------
__global__ void __launch_bounds__(256) build_c_kernel() {
    extern __shared__ float csm[];
    float* att_s = csm;
    float* mout_s = csm + 4225;
    int blk = blockIdx.x;                    // b*16 + h*2 + p
    int b = blk >> 4;
    int hp = blk & 15;
    int hd = hp >> 1, p = hp & 1;
    int tid = threadIdx.x;
    int bh = b * 8 + hd;
    for (int idx = tid; idx < 4225; idx += 256)
        att_s[idx] = g_att[(size_t)bh * 4225 + idx];
    for (int idx = tid; idx < 8320; idx += 256)
        mout_s[idx] = g_Mout[(size_t)hp * 8320 + idx];
    __syncthreads();
    for (int idx = tid; idx < 8320; idx += 256) {
        int o = idx / 65, y = idx - o * 65;
        float acc = 0.f;
        #pragma unroll 5
        for (int x = 0; x < 65; x++)
            acc += att_s[x * 65 + y] * mout_s[x * 128 + o];
        int k = hd * 130 + 2 * y + p;
        __nv_bfloat16 hi = __float2bfloat16(acc);
        size_t off = ((size_t)b * 128 + o) * NKP_ + k;
        g_CThi[off] = hi;
        g_CTlo[off] = __float2bfloat16(acc - __bfloat162float(hi));
    }
}

// ---------------- GEMM2: m-tile 128, 3-stage pipeline ----------------
// stage 64KB: Ahi 16K @0, Alo @16384, Bhi @32768, Blo @49152
#define G2_STG 65536
#define G2_TOT (3 * G2_STG)   // 192KB
__device__ __forceinline__ void g2_load(uint32_t sst, int bm,
                                        const __nv_bfloat16* CThi,
                                        const __nv_bfloat16* CTlo,
                                        int k0, int tid) {
    for (int u = tid; u < 1024; u += 256) {
        int r = u >> 3, cb = (u & 7) * 16;
        uint32_t d = swz64(r, cb);
        size_t asrc = ((size_t)(bm + r) * NKP_ + k0) * 2 + cb;
        size_t bsrc = ((size_t)r * NKP_ + k0) * 2 + cb;
        cp16(sst + d,         (const char*)g_Vhi + asrc);
        cp16(sst + 16384 + d, (const char*)g_Vlo + asrc);
        cp16(sst + 32768 + d, (const char*)CThi + bsrc);
        cp16(sst + 49152 + d, (const char*)CTlo + bsrc);
    }
}

__global__ void __launch_bounds__(256, 1) gemm2_tc(float* __restrict__ out,
                                                   const float* __restrict__ bias) {
    extern __shared__ char smem[];
    uint32_t sb = smem_u32(smem);
    int tid = threadIdx.x;
    int lane = tid & 31, wid = tid >> 5;
    int wm = wid & 3, wn = wid >> 2;     // 4 x 2 warps over 128 x 128
    int bm = blockIdx.x * 128;
    int b = bm >> 11;
    const __nv_bfloat16* CThi = g_CThi + (size_t)b * 128 * NKP_;
    const __nv_bfloat16* CTlo = g_CTlo + (size_t)b * 128 * NKP_;

    float c[2][8][4];
    #pragma unroll
    for (int i = 0; i < 2; i++)
        #pragma unroll
        for (int j = 0; j < 8; j++)
            #pragma unroll
            for (int k = 0; k < 4; k++) c[i][j][k] = 0.f;

    g2_load(sb, bm, CThi, CTlo, 0, tid);  cp_commit();
    g2_load(sb + G2_STG, bm, CThi, CTlo, 64, tid);  cp_commit();
    g2_load(sb + 2 * G2_STG, bm, CThi, CTlo, 128, tid);  cp_commit();

    for (int kc = 0; kc < 18; kc++) {
        cp_wait2();
        __syncthreads();
        uint32_t sst = sb + (kc % 3) * G2_STG;
        mma_chunk64(sst, sst + 16384, sst + 32768, sst + 49152, lane, wm, wn, c);
        __syncthreads();
        if (kc + 3 < 18) {
            g2_load(sst, bm, CThi, CTlo, (kc + 3) * 64, tid);
            cp_commit();
        }
    }

    int g = lane >> 2, cp2 = (lane & 3) * 2;
    #pragma unroll
    for (int tm = 0; tm < 2; tm++)
        #pragma unroll
        for (int hf = 0; hf < 2; hf++) {
            size_t row = (size_t)bm + wm * 32 + tm * 16 + hf * 8 + g;
            float* dst = out + row * 128;
            #pragma unroll
            for (int tn = 0; tn < 8; tn++) {
                int col = wn * 64 + tn * 8 + cp2;
                float2 bv = *(const float2*)(bias + col);
                *(float2*)(dst + col) = make_float2(c[tm][tn][hf * 2] + bv.x,
                                                    c[tm][tn][hf * 2 + 1] + bv.y);
            }
        }
}

// ---------------- launch ----------------
extern "C" void kernel_launch(void* const* d_in, const int* in_sizes, int n_in,
                              void* d_out, int out_size) {
    const float* x     = (const float*)d_in[0];
    const float* w_qkv = (const float*)d_in[1];
    const float* w_out = (const float*)d_in[2];
    const float* b_out = (const float*)d_in[3];
    float* out = (float*)d_out;

    cudaFuncSetAttribute(gemm1_tc, cudaFuncAttributeMaxDynamicSharedMemorySize, G1_TOT);
    cudaFuncSetAttribute(gemm2_tc, cudaFuncAttributeMaxDynamicSharedMemorySize, G2_TOT);
    cudaFuncSetAttribute(build_c_kernel, cudaFuncAttributeMaxDynamicSharedMemorySize,
                         (4225 + 8320) * 4);

    split_x_kernel<<<ROWS_ * D_ / 4 / 256, 256>>>(x);
    build_w1_kernel<<<480, 256>>>(w_qkv);
    build_mout_kernel<<<130, 256>>>(w_out);
    gemm1_tc<<<dim3(ROWS_ / 128, 2), 256, G1_TOT>>>();
    att_partial_kernel<<<dim3(EQ_, B_ * H_), 256>>>();
    att_softmax_kernel<<<B_ * H_, 256>>>();
    build_c_kernel<<<B_ * H_ * 2, 256, (4225 + 8320) * 4>>>();
    gemm2_tc<<<ROWS_ / 128, 256, G2_TOT>>>(out, b_out);
}

// round 8
// speedup vs baseline: 1.1750x; 1.1750x over previous
#include <cuda_runtime.h>
#include <cuda_bf16.h>
#include <cstdint>
#include <math.h>

// Problem constants
#define B_    16
#define N_    2048
#define D_    128
#define H_    8
#define F_    65
#define ROWS_ 32768
#define N1_   2080       // q,k only: 2 regions * 8 heads * 130 (re/im interleaved u=2f+p)
#define N1P_  2176       // 17 n-tiles of 128
#define NK_   1040       // v feature dim (fp32 path now)
#define SCALE_ (1.0f/65.0f)
#define EQ_   8          // att e-chunks

// ---------------- scratch (static device, no allocation) ----------------
__device__ __nv_bfloat16 g_Xhi[(size_t)ROWS_ * D_];
__device__ __nv_bfloat16 g_Xlo[(size_t)ROWS_ * D_];
__device__ __nv_bfloat16 g_W1T_hi[N1P_ * D_];    // [2176][128] q,k folded weights
__device__ __nv_bfloat16 g_W1T_lo[N1P_ * D_];
__device__ float g_W1v[D_ * NK_];                // [d][k] v folded weights, fp32
__device__ float g_Mout[H_ * 2 * F_ * D_];       // [h][p][x][o]
__device__ float g_aq[(size_t)ROWS_ * H_ * F_];  // [row][h][f]
__device__ float g_ak[(size_t)ROWS_ * H_ * F_];
__device__ float g_attp[B_ * H_ * EQ_ * F_ * F_];
__device__ float g_att[B_ * H_ * F_ * F_];
__device__ float g_C[B_ * NK_ * D_];             // [b][k][o] fp32 att-mixed Mout
__device__ __nv_bfloat16 g_DThi[B_ * D_ * D_];   // [b][o][d] folded W1v@C, split
__device__ __nv_bfloat16 g_DTlo[B_ * D_ * D_];

// ---------------- helpers ----------------
__device__ __forceinline__ uint32_t smem_u32(const void* p) {
    uint32_t a;
    asm("{ .reg .u64 t; cvta.to.shared.u64 t, %1; cvt.u32.u64 %0, t; }" : "=r"(a) : "l"(p));
    return a;
}
__device__ __forceinline__ void ldsm_x4(uint32_t* r, uint32_t addr) {
    asm volatile("ldmatrix.sync.aligned.m8n8.x4.shared.b16 {%0,%1,%2,%3}, [%4];"
                 : "=r"(r[0]), "=r"(r[1]), "=r"(r[2]), "=r"(r[3]) : "r"(addr));
}
__device__ __forceinline__ void mma16816(float* c, const uint32_t* a, const uint32_t* b) {
    asm volatile("mma.sync.aligned.m16n8k16.row.col.f32.bf16.bf16.f32 "
                 "{%0,%1,%2,%3}, {%4,%5,%6,%7}, {%8,%9}, {%0,%1,%2,%3};"
                 : "+f"(c[0]), "+f"(c[1]), "+f"(c[2]), "+f"(c[3])
                 : "r"(a[0]), "r"(a[1]), "r"(a[2]), "r"(a[3]), "r"(b[0]), "r"(b[1]));
}
__device__ __forceinline__ uint32_t pack_bf(__nv_bfloat16 a, __nv_bfloat16 b) {
    __nv_bfloat162 p = __halves2bfloat162(a, b);
    return *reinterpret_cast<uint32_t*>(&p);
}
// swizzled offset within a [rows][64 bf16] tile (row = 128 bytes)
__device__ __forceinline__ uint32_t swz64(int row, int colbyte) {
    return (uint32_t)(row * 128 + (colbyte ^ ((row & 7) << 4)));
}
__device__ __forceinline__ void cp16(uint32_t dst, const void* src) {
    asm volatile("cp.async.cg.shared.global [%0], [%1], 16;" :: "r"(dst), "l"(src));
}
__device__ __forceinline__ void cp_commit() { asm volatile("cp.async.commit_group;"); }
__device__ __forceinline__ void cp_wait0() { asm volatile("cp.async.wait_group 0;" ::: "memory"); }
__device__ __forceinline__ void cp_wait1() { asm volatile("cp.async.wait_group 1;" ::: "memory"); }

// 3-pass mma sweep over one resident [*x64] K-chunk (4 k-steps)
__device__ __forceinline__ void mma_chunk64(uint32_t sAhi, uint32_t sAlo,
                                            uint32_t sBhi, uint32_t sBlo,
                                            int lane, int wm, int wn, float c[2][8][4]) {
    #pragma unroll
    for (int p = 0; p < 3; p++) {
        uint32_t sA = (p == 2) ? sAlo : sAhi;
        uint32_t sB = (p == 1) ? sBlo : sBhi;
        #pragma unroll
        for (int ks = 0; ks < 4; ks++) {
            int colb = ks * 32 + (lane >> 4) * 16;
            uint32_t a[2][4];
            #pragma unroll
            for (int tm = 0; tm < 2; tm++) {
                int r = wm * 32 + tm * 16 + (lane & 15);
                ldsm_x4(a[tm], sA + swz64(r, colb));
            }
            uint32_t b[8][2];
            #pragma unroll
            for (int ng = 0; ng < 4; ng++) {
                int n = wn * 64 + ng * 16 + (lane & 15);
                uint32_t q[4];
                ldsm_x4(q, sB + swz64(n, colb));
                b[2 * ng][0] = q[0]; b[2 * ng + 1][0] = q[1];
                b[2 * ng][1] = q[2]; b[2 * ng + 1][1] = q[3];
            }
            #pragma unroll
            for (int tm = 0; tm < 2; tm++)
                #pragma unroll
                for (int tn = 0; tn < 8; tn++)
                    mma16816(c[tm][tn], a[tm], b[tn]);
        }
    }
}

// ---------------- X pre-split ----------------
__global__ void split_x_kernel(const float* __restrict__ X) {
    size_t i = (size_t)blockIdx.x * blockDim.x + threadIdx.x;
    float4 v = ((const float4*)X)[i];
    __nv_bfloat16 h0 = __float2bfloat16(v.x), h1 = __float2bfloat16(v.y);
    __nv_bfloat16 h2 = __float2bfloat16(v.z), h3 = __float2bfloat16(v.w);
    ((uint2*)g_Xhi)[i] = make_uint2(pack_bf(h0, h1), pack_bf(h2, h3));
    ((uint2*)g_Xlo)[i] = make_uint2(
        pack_bf(__float2bfloat16(v.x - __bfloat162float(h0)),
                __float2bfloat16(v.y - __bfloat162float(h1))),
        pack_bf(__float2bfloat16(v.z - __bfloat162float(h2)),
                __float2bfloat16(v.w - __bfloat162float(h3))));
}

// ---------------- weight folding: q,k (bf16 split), interleaved u=2f+p ----------------
__global__ void build_w1_kernel(const float* __restrict__ w_qkv) {
    __shared__ float cs[128], sn[128];
    int t = threadIdx.x;
    if (t < 128) {
        float ang = (float)t / 64.0f;
        cs[t] = cospif(ang);
        sn[t] = sinpif(ang);
    }
    __syncthreads();
    const int total = N1P_ * D_;
    for (int idx = blockIdx.x * blockDim.x + t; idx < total; idx += gridDim.x * blockDim.x) {
        int c = idx >> 7, d = idx & 127;
        float acc = 0.f;
        if (c < N1_) {
            int region = c / 1040;      // 0=q, 1=k
        int cc = c - region * 1040;
            int hd = cc / 130;
            int u = cc - hd * 130;
            int f = u >> 1;
            const float* w = w_qkv + (size_t)d * 3072 + region * 1024 + hd * 128;
            if ((u & 1) == 0) {
                #pragma unroll 8
                for (int dd = 0; dd < 128; dd++) acc += w[dd] * cs[(f * dd) & 127];
            } else {
                #pragma unroll 8
                for (int dd = 0; dd < 128; dd++) acc -= w[dd] * sn[(f * dd) & 127];
            }
            acc *= SCALE_;
        }
        __nv_bfloat16 hi = __float2bfloat16(acc);
        g_W1T_hi[idx] = hi;
        g_W1T_lo[idx] = __float2bfloat16(acc - __bfloat162float(hi));
    }
}

// ---------------- weight folding: v (fp32, [d][k], k = hd*130+2f+p) ----------------
__global__ void build_w1v_kernel(const float* __restrict__ w_qkv) {
    __shared__ float cs[128], sn[128];
    int t = threadIdx.x;
    if (t < 128) {
        float ang = (float)t / 64.0f;
        cs[t] = cospif(ang);
        sn[t] = sinpif(ang);
    }
    __syncthreads();
    const int total = D_ * NK_;
    for (int idx = blockIdx.x * blockDim.x + t; idx < total; idx += gridDim.x * blockDim.x) {
        int d = idx / NK_, k = idx - d * NK_;
        int hd = k / 130;
        int u = k - hd * 130;
        int f = u >> 1;
        const float* w = w_qkv + (size_t)d * 3072 + 2048 + hd * 128;
        float acc = 0.f;
        if ((u & 1) == 0) {
            #pragma unroll 8
            for (int dd = 0; dd < 128; dd++) acc += w[dd] * cs[(f * dd) & 127];
        } else {
            #pragma unroll 8
            for (int dd = 0; dd < 128; dd++) acc -= w[dd] * sn[(f * dd) & 127];
        }
        g_W1v[idx] = acc;
    }
}

__global__ void build_mout_kernel(const float* __restrict__ w_out) {
    __shared__ float cs[128], sn[128];
    int t = threadIdx.x;
    if (t < 128) {
        float ang = (float)t / 64.0f;
        cs[t] = cospif(ang);
        sn[t] = sinpif(ang);
    }
    __syncthreads();
    const int total = H_ * 2 * F_ * D_;
    for (int idx = blockIdx.x * blockDim.x + t; idx < total; idx += gridDim.x * blockDim.x) {
        int o = idx & 127;
        int r = idx >> 7;
        int x = r % 65;
        int hp = r / 65;
        int p = hp & 1, hd = hp >> 1;
        float acc = 0.f;
        if (p == 0) {
            #pragma unroll 8
            for (int t2 = 0; t2 < 128; t2++)
                acc += cs[(x * t2) & 127] * w_out[(size_t)(hd * 128 + t2) * 128 + o];
            acc *= ((x == 0 || x == 64) ? 1.0f : 2.0f) / 128.0f;
        } else if (x != 0 && x != 64) {
            #pragma unroll 8
            for (int t2 = 0; t2 < 128; t2++)
                acc -= sn[(x * t2) & 127] * w_out[(size_t)(hd * 128 + t2) * 128 + o];
            acc *= 2.0f / 128.0f;
        }
        g_Mout[idx] = acc;
    }
}

// ---------------- GEMM1: |X@W1_qk| -> aq, ak (m256 x n128, 512 thr, 2-stage) ----------------
// stage: AHI 32K @0, ALO @32768, BHI 16K @65536, BLO @81920; stride 98304
#define G1_STG 98304
__device__ __forceinline__ void g1_load(uint32_t sst, int bm, int bn, int k0, int tid) {
    #pragma unroll
    for (int u = tid; u < 2048; u += 512) {
        int r = u >> 3, cb = (u & 7) * 16;
        uint32_t d = swz64(r, cb);
        cp16(sst + d,         (const char*)g_Xhi + ((size_t)(bm + r) * 128 + k0) * 2 + cb);
        cp16(sst + 32768 + d, (const char*)g_Xlo + ((size_t)(bm + r) * 128 + k0) * 2 + cb);
    }
    #pragma unroll
    for (int u = tid; u < 1024; u += 512) {
        int r = u >> 3, cb = (u & 7) * 16;
        uint32_t d = swz64(r, cb);
        cp16(sst + 65536 + d, (const char*)g_W1T_hi + ((size_t)(bn + r) * 128 + k0) * 2 + cb);
        cp16(sst + 81920 + d, (const char*)g_W1T_lo + ((size_t)(bn + r) * 128 + k0) * 2 + cb);
    }
}

__global__ void __launch_bounds__(512, 1) gemm1_tc() {
    extern __shared__ char smem[];
    uint32_t sb = smem_u32(smem);
    int tid = threadIdx.x;
    int lane = tid & 31, wid = tid >> 5;
    int wm = wid & 7, wn = wid >> 3;      // 8 x 2 warps over 256 x 128
    int bm = blockIdx.y * 256, bn = blockIdx.x * 128;

    g1_load(sb, bm, bn, 0, tid);  cp_commit();
    g1_load(sb + G1_STG, bm, bn, 64, tid);  cp_commit();

    float c[2][8][4];
    #pragma unroll
    for (int i = 0; i < 2; i++)
        #pragma unroll
        for (int j = 0; j < 8; j++)
            #pragma unroll
            for (int k = 0; k < 4; k++) c[i][j][k] = 0.f;

    cp_wait1();
    __syncthreads();
    mma_chunk64(sb, sb + 32768, sb + 65536, sb + 81920, lane, wm, wn, c);
    cp_wait0();
    __syncthreads();
    mma_chunk64(sb + G1_STG, sb + G1_STG + 32768, sb + G1_STG + 65536,
                sb + G1_STG + 81920, lane, wm, wn, c);

    // epilogue: only |q|,|k| (no conversions, 1 STG per value)
    int g = lane >> 2, cp2 = (lane & 3) * 2;
    #pragma unroll
    for (int tn = 0; tn < 8; tn++) {
        int col = bn + wn * 64 + tn * 8 + cp2;   // even
        if (col >= N1_) continue;
        int region = (col >= 1040) ? 1 : 0;
        int cc = col - region * 1040;
        int hd = cc / 130;
        int uu = cc - hd * 130;
        int f = uu >> 1;
        float* base = region ? g_ak : g_aq;
        #pragma unroll
        for (int tm = 0; tm < 2; tm++)
            #pragma unroll
            for (int hf = 0; hf < 2; hf++) {
                size_t row = (size_t)bm + wm * 32 + tm * 16 + hf * 8 + g;
                float re = c[tm][tn][hf * 2], im = c[tm][tn][hf * 2 + 1];
                base[(row * 8 + hd) * 65 + f] = sqrtf(re * re + im * im);
            }
    }
}

// ---------------- att partial: [f][e] transposed smem, float4 over e ----------------
__global__ void __launch_bounds__(256) att_partial_kernel() {
    __shared__ float aqs[65 * 68];
    __shared__ float aks[65 * 68];
    int bh = blockIdx.y;
    int b = bh >> 3, h = bh & 7;
    int chunk = blockIdx.x;
    int tid = threadIdx.x;
    int tx = tid & 15, ty = tid >> 4;
    int xs[5], ys[5];
    #pragma unroll
    for (int i = 0; i < 5; i++) {
        int x = tx + 16 * i; xs[i] = (x < 65) ? x : 0;
        int y = ty + 16 * i; ys[i] = (y < 65) ? y : 0;
    }
    float acc[5][5];
    #pragma unroll
    for (int i = 0; i < 5; i++)
        #pragma unroll
        for (int j = 0; j < 5; j++) acc[i][j] = 0.f;

    int ebase = chunk * (2048 / EQ_);
    for (int e0 = ebase; e0 < ebase + 2048 / EQ_; e0 += 64) {
        for (int idx = tid; idx < 4160; idx += 256) {
            int r = idx / 65, f = idx - r * 65;
            size_t gidx = ((size_t)((b * 2048 + e0 + r) * 8 + h)) * 65 + f;
            aqs[f * 68 + r] = g_aq[gidx];
            aks[f * 68 + r] = g_ak[gidx];
        }
        __syncthreads();
        #pragma unroll 2
        for (int e4 = 0; e4 < 64; e4 += 4) {
            float4 av[5], bv[5];
            #pragma unroll
            for (int i = 0; i < 5; i++) av[i] = *(const float4*)&aqs[xs[i] * 68 + e4];
            #pragma unroll
            for (int j = 0; j < 5; j++) bv[j] = *(const float4*)&aks[ys[j] * 68 + e4];
            #pragma unroll
            for (int i = 0; i < 5; i++)
                #pragma unroll
                for (int j = 0; j < 5; j++) {
                    acc[i][j] += av[i].x * bv[j].x;
                    acc[i][j] += av[i].y * bv[j].y;
                    acc[i][j] += av[i].z * bv[j].z;
                    acc[i][j] += av[i].w * bv[j].w;
                }
        }
        __syncthreads();
    }
    float* dst = g_attp + (size_t)(bh * EQ_ + chunk) * 4225;
    #pragma unroll
    for (int i = 0; i < 5; i++) {
        int x = tx + 16 * i;
        if (x < 65)
            #pragma unroll
            for (int j = 0; j < 5; j++) {
                int y = ty + 16 * j;
                if (y < 65) dst[x * 65 + y] = acc[i][j];
            }
    }
}

// ---------------- softmax ----------------
__global__ void __launch_bounds__(256) att_softmax_kernel() {
    __shared__ float sm[4225];
    int bh = blockIdx.x;
    int tid = threadIdx.x;
    const float* p0 = g_attp + (size_t)(bh * EQ_) * 4225;
    for (int idx = tid; idx < 4225; idx += 256) {
        float s = 0.f;
        #pragma unroll
        for (int q = 0; q < EQ_; q++) s += p0[q * 4225 + idx];
        sm[idx] = s;
    }
    __syncthreads();
    int warp = tid >> 5, lane = tid & 31;
    for (int x = warp; x < 65; x += 8) {
        float m = -3.4e38f;
        for (int y = lane; y < 65; y += 32) m = fmaxf(m, sm[x * 65 + y]);
        #pragma unroll
        for (int o = 16; o; o >>= 1) m = fmaxf(m, __shfl_xor_sync(0xffffffffu, m, o));
        float s = 0.f;
        for (int y = lane; y < 65; y += 32) {
            float v = expf(sm[x * 65 + y] - m);
            sm[x * 65 + y] = v;
            s += v;
        }
        #pragma unroll
        for (int o = 16; o; o >>= 1) s += __shfl_xor_sync(0xffffffffu, s, o);
        float inv = 1.0f / s;
        for (int y = lane; y < 65; y += 32)
            g_att[(size_t)bh * 4225 + x * 65 + y] = sm[x * 65 + y] * inv;
    }
}

// ---------------- build C_b: C[b][hd*130+2y+p][o] = sum_x att[x,y]*Mout[hd,p,x,o] ----------------
__global__ void __launch_bounds__(256) build_c_kernel() {
    extern __shared__ float csm[];
    float* att_s = csm;
    float* mout_s = csm + 4225;
    int blk = blockIdx.x;                    // b*16 + h*2 + p
    int b = blk >> 4;
    int hp = blk & 15;
    int hd = hp >> 1, p = hp & 1;
    int tid = threadIdx.x;
    int bh = b * 8 + hd;
    for (int idx = tid; idx < 4225; idx += 256)
        att_s[idx] = g_att[(size_t)bh * 4225 + idx];
    for (int idx = tid; idx < 8320; idx += 256)
        mout_s[idx] = g_Mout[(size_t)hp * 8320 + idx];
    __syncthreads();
    for (int idx = tid; idx < 8320; idx += 256) {
        int o = idx / 65, y = idx - o * 65;
        float acc = 0.f;
        #pragma unroll 5
        for (int x = 0; x < 65; x++)
            acc += att_s[x * 65 + y] * mout_s[x * 128 + o];
        int k = hd * 130 + 2 * y + p;
        g_C[((size_t)b * NK_ + k) * 128 + o] = acc;
    }
}

// ---------------- build D_b = W1v @ C_b, split to DT hi/lo ----------------
__global__ void __launch_bounds__(256) build_d_kernel() {
    __shared__ float Wvs[128 * 65];   // [d][kk]
    __shared__ float Cs[65 * 32];     // [kk][oo]
    int b = blockIdx.x;
    int o0 = blockIdx.y * 32;
    int tid = threadIdx.x;
    int ol = tid & 31, dg = tid >> 5;  // o lane, d group (0..7)
    float acc[16];
    #pragma unroll
    for (int i = 0; i < 16; i++) acc[i] = 0.f;

    for (int k0 = 0; k0 < NK_; k0 += 65) {
        __syncthreads();
        for (int u = tid; u < 8320; u += 256) {
            int d = u / 65, kk = u - d * 65;
            Wvs[u] = g_W1v[(size_t)d * NK_ + k0 + kk];
        }
        for (int u = tid; u < 2080; u += 256) {
            int kk = u >> 5, oo = u & 31;
            Cs[u] = g_C[((size_t)b * NK_ + k0 + kk) * 128 + o0 + oo];
        }
        __syncthreads();
        #pragma unroll 5
        for (int kk = 0; kk < 65; kk++) {
            float cv = Cs[kk * 32 + ol];
            #pragma unroll
            for (int i = 0; i < 16; i++)
                acc[i] += Wvs[(dg + 8 * i) * 65 + kk] * cv;
        }
    }
    #pragma unroll
    for (int i = 0; i < 16; i++) {
        int d = dg + 8 * i;
        __nv_bfloat16 hi = __float2bfloat16(acc[i]);
        size_t off = ((size_t)b * 128 + o0 + ol) * 128 + d;
        g_DThi[off] = hi;
        g_DTlo[off] = __float2bfloat16(acc[i] - __bfloat162float(hi));
    }
}

// ---------------- final GEMM: out = X @ D_b + bias (m256, K=128, load-once) ----------------
#define FG_AHI 0
#define FG_ALO 65536
#define FG_BHI 131072
#define FG_BLO 163840
#define FG_TOT 196608
__global__ void __launch_bounds__(512, 1) final_gemm(float* __restrict__ out,
                                                     const float* __restrict__ bias) {
    extern __shared__ char smem[];
    uint32_t sb = smem_u32(smem);
    int tid = threadIdx.x;
    int lane = tid & 31, wid = tid >> 5;
    int wm = wid & 7, wn = wid >> 3;     // 8 x 2 warps over 256 x 128
    int bm = blockIdx.x * 256;
    int b = bm >> 11;

    #pragma unroll
    for (int u = tid; u < 4096; u += 512) {
        int r = u >> 4, seg = u & 15;
        int ch = seg >> 3, cb = (seg & 7) * 16;
        uint32_t d = ch * 32768 + swz64(r, cb);
        size_t src = (size_t)(bm + r) * 256 + ch * 128 + cb;
        cp16(sb + FG_AHI + d, (const char*)g_Xhi + src);
        cp16(sb + FG_ALO + d, (const char*)g_Xlo + src);
    }
    #pragma unroll
    for (int u = tid; u < 2048; u += 512) {
        int r = u >> 4, seg = u & 15;
        int ch = seg >> 3, cb = (seg & 7) * 16;
        uint32_t d = ch * 16384 + swz64(r, cb);
        size_t src = ((size_t)(b * 128 + r)) * 256 + ch * 128 + cb;
        cp16(sb + FG_BHI + d, (const char*)g_DThi + src);
        cp16(sb + FG_BLO + d, (const char*)g_DTlo + src);
    }
    cp_commit();
    cp_wait0();
    __syncthreads();

    float c[2][8][4];
    #pragma unroll
    for (int i = 0; i < 2; i++)
        #pragma unroll
        for (int j = 0; j < 8; j++)
            #pragma unroll
            for (int k = 0; k < 4; k++) c[i][j][k] = 0.f;

    #pragma unroll
    for (int ch = 0; ch < 2; ch++)
        mma_chunk64(sb + FG_AHI + ch * 32768, sb + FG_ALO + ch * 32768,
                    sb + FG_BHI + ch * 16384, sb + FG_BLO + ch * 16384,
                    lane, wm, wn, c);

    int g = lane >> 2, cp2 = (lane & 3) * 2;
    #pragma unroll
    for (int tm = 0; tm < 2; tm++)
        #pragma unroll
        for (int hf = 0; hf < 2; hf++) {
            size_t row = (size_t)bm + wm * 32 + tm * 16 + hf * 8 + g;
            float* dst = out + row * 128;
            #pragma unroll
            for (int tn = 0; tn < 8; tn++) {
                int col = wn * 64 + tn * 8 + cp2;
                float2 bv = *(const float2*)(bias + col);
                *(float2*)(dst + col) = make_float2(c[tm][tn][hf * 2] + bv.x,
                                                    c[tm][tn][hf * 2 + 1] + bv.y);
            }
        }
}

// ---------------- launch ----------------
extern "C" void kernel_launch(void* const* d_in, const int* in_sizes, int n_in,
                              void* d_out, int out_size) {
    const float* x     = (const float*)d_in[0];
    const float* w_qkv = (const float*)d_in[1];
    const float* w_out = (const float*)d_in[2];
    const float* b_out = (const float*)d_in[3];
    float* out = (float*)d_out;

    cudaFuncSetAttribute(gemm1_tc, cudaFuncAttributeMaxDynamicSharedMemorySize, 2 * G1_STG);
    cudaFuncSetAttribute(final_gemm, cudaFuncAttributeMaxDynamicSharedMemorySize, FG_TOT);
    cudaFuncSetAttribute(build_c_kernel, cudaFuncAttributeMaxDynamicSharedMemorySize,
                         (4225 + 8320) * 4);

    split_x_kernel<<<ROWS_ * D_ / 4 / 256, 256>>>(x);
    build_w1_kernel<<<480, 256>>>(w_qkv);
    build_w1v_kernel<<<520, 256>>>(w_qkv);
    build_mout_kernel<<<130, 256>>>(w_out);
    gemm1_tc<<<dim3(N1P_ / 128, ROWS_ / 256), 512, 2 * G1_STG>>>();
    att_partial_kernel<<<dim3(EQ_, B_ * H_), 256>>>();
    att_softmax_kernel<<<B_ * H_, 256>>>();
    build_c_kernel<<<B_ * H_ * 2, 256, (4225 + 8320) * 4>>>();
    build_d_kernel<<<dim3(B_, 4), 256>>>();
    final_gemm<<<ROWS_ / 256, 512, FG_TOT>>>(out, b_out);
}

// round 9
// speedup vs baseline: 1.5613x; 1.3288x over previous
#include <cuda_runtime.h>
#include <cuda_bf16.h>
#include <cstdint>
#include <math.h>

// Problem constants
#define B_    16
#define N_    2048
#define D_    128
#define H_    8
#define F_    65
#define ROWS_ 32768
#define N1_   2080       // q,k only: 2 regions * 8 heads * 130 (re/im interleaved u=2f+p)
#define N1P_  2176       // 17 n-tiles of 128
#define NK_   1040       // v feature dim (fp32 path)
#define SCALE_ (1.0f/65.0f)
#define EQ_   8          // att e-chunks

// ---------------- scratch (static device, no allocation) ----------------
__device__ __nv_bfloat16 g_Xhi[(size_t)ROWS_ * D_];
__device__ __nv_bfloat16 g_Xlo[(size_t)ROWS_ * D_];
__device__ __nv_bfloat16 g_W1T_hi[N1P_ * D_];    // [2176][128] q,k folded weights
__device__ __nv_bfloat16 g_W1T_lo[N1P_ * D_];
__device__ float g_W1v[D_ * NK_];                // [d][k] v folded weights, fp32
__device__ float g_Mout[H_ * 2 * F_ * D_];       // [h][p][x][o]
__device__ float g_aq[(size_t)ROWS_ * H_ * F_];  // [row][h][f]
__device__ float g_ak[(size_t)ROWS_ * H_ * F_];
__device__ float g_attp[B_ * H_ * EQ_ * F_ * F_];
__device__ float g_att[B_ * H_ * F_ * F_];
__device__ float g_C[B_ * NK_ * D_];             // [b][k][o]
__device__ __nv_bfloat16 g_DThi[B_ * D_ * D_];   // [b][o][d]
__device__ __nv_bfloat16 g_DTlo[B_ * D_ * D_];

// ---------------- helpers ----------------
__device__ __forceinline__ uint32_t smem_u32(const void* p) {
    uint32_t a;
    asm("{ .reg .u64 t; cvta.to.shared.u64 t, %1; cvt.u32.u64 %0, t; }" : "=r"(a) : "l"(p));
    return a;
}
__device__ __forceinline__ void ldsm_x4(uint32_t* r, uint32_t addr) {
    asm volatile("ldmatrix.sync.aligned.m8n8.x4.shared.b16 {%0,%1,%2,%3}, [%4];"
                 : "=r"(r[0]), "=r"(r[1]), "=r"(r[2]), "=r"(r[3]) : "r"(addr));
}
__device__ __forceinline__ void mma16816(float* c, const uint32_t* a, const uint32_t* b) {
    asm volatile("mma.sync.aligned.m16n8k16.row.col.f32.bf16.bf16.f32 "
                 "{%0,%1,%2,%3}, {%4,%5,%6,%7}, {%8,%9}, {%0,%1,%2,%3};"
                 : "+f"(c[0]), "+f"(c[1]), "+f"(c[2]), "+f"(c[3])
                 : "r"(a[0]), "r"(a[1]), "r"(a[2]), "r"(a[3]), "r"(b[0]), "r"(b[1]));
}
__device__ __forceinline__ uint32_t pack_bf(__nv_bfloat16 a, __nv_bfloat16 b) {
    __nv_bfloat162 p = __halves2bfloat162(a, b);
    return *reinterpret_cast<uint32_t*>(&p);
}
// swizzled offset within a [rows][64 bf16] tile (row = 128 bytes)
__device__ __forceinline__ uint32_t swz64(int row, int colbyte) {
    return (uint32_t)(row * 128 + (colbyte ^ ((row & 7) << 4)));
}
__device__ __forceinline__ void cp16(uint32_t dst, const void* src) {
    asm volatile("cp.async.cg.shared.global [%0], [%1], 16;" :: "r"(dst), "l"(src));
}
__device__ __forceinline__ void cp_commit() { asm volatile("cp.async.commit_group;"); }
__device__ __forceinline__ void cp_wait0() { asm volatile("cp.async.wait_group 0;" ::: "memory"); }
__device__ __forceinline__ void cp_wait1() { asm volatile("cp.async.wait_group 1;" ::: "memory"); }

// fused 3-product sweep over one resident [*x64] K-chunk (4 k-steps).
// Per k-step: 12 ldsm feed 48 mma (A-hi reused for B-hi/B-lo; B-hi reused for A-lo).
__device__ __forceinline__ void mma_chunk64(uint32_t sAhi, uint32_t sAlo,
                                            uint32_t sBhi, uint32_t sBlo,
                                            int lane, int wm, int wn, float c[2][8][4]) {
    #pragma unroll
    for (int ks = 0; ks < 4; ks++) {
        int colb = ks * 32 + (lane >> 4) * 16;
        int ar = wm * 32 + (lane & 15);
        uint32_t ahi[2][4], alo[2][4];
        #pragma unroll
        for (int tm = 0; tm < 2; tm++)
            ldsm_x4(ahi[tm], sAhi + swz64(ar + tm * 16, colb));
        uint32_t bhi[8][2], blo[8][2];
        #pragma unroll
        for (int ng = 0; ng < 4; ng++) {
            int n = wn * 64 + ng * 16 + (lane & 15);
            uint32_t q[4];
            ldsm_x4(q, sBhi + swz64(n, colb));
            bhi[2 * ng][0] = q[0]; bhi[2 * ng + 1][0] = q[1];
            bhi[2 * ng][1] = q[2]; bhi[2 * ng + 1][1] = q[3];
        }
        #pragma unroll
        for (int tm = 0; tm < 2; tm++)
            #pragma unroll
            for (int tn = 0; tn < 8; tn++)
                mma16816(c[tm][tn], ahi[tm], bhi[tn]);
        #pragma unroll
        for (int ng = 0; ng < 4; ng++) {
            int n = wn * 64 + ng * 16 + (lane & 15);
            uint32_t q[4];
            ldsm_x4(q, sBlo + swz64(n, colb));
            blo[2 * ng][0] = q[0]; blo[2 * ng + 1][0] = q[1];
            blo[2 * ng][1] = q[2]; blo[2 * ng + 1][1] = q[3];
        }
        #pragma unroll
        for (int tm = 0; tm < 2; tm++)
            #pragma unroll
            for (int tn = 0; tn < 8; tn++)
                mma16816(c[tm][tn], ahi[tm], blo[tn]);
        #pragma unroll
        for (int tm = 0; tm < 2; tm++)
            ldsm_x4(alo[tm], sAlo + swz64(ar + tm * 16, colb));
        #pragma unroll
        for (int tm = 0; tm < 2; tm++)
            #pragma unroll
            for (int tn = 0; tn < 8; tn++)
                mma16816(c[tm][tn], alo[tm], bhi[tn]);
    }
}

// ---------------- merged prep: split_x + build_w1 + build_w1v + build_mout ----------------
#define PREP_SPLIT  4096                    // 4096 * 256 = 1M float4
#define PREP_W1     1088                    // 278528 elements
#define PREP_W1V    520                     // 133120 elements
#define PREP_MOUT   520                     // 133120 elements
#define PREP_TOTAL  (PREP_SPLIT + PREP_W1 + PREP_W1V + PREP_MOUT)

__global__ void __launch_bounds__(256) prep_kernel(const float* __restrict__ X,
                                                   const float* __restrict__ w_qkv,
                                                   const float* __restrict__ w_out) {
    __shared__ float cs[128], sn[128];
    int tid = threadIdx.x;
    int blk = blockIdx.x;
    if (blk < PREP_SPLIT) {
        size_t i = (size_t)blk * 256 + tid;
        float4 v = ((const float4*)X)[i];
        __nv_bfloat16 h0 = __float2bfloat16(v.x), h1 = __float2bfloat16(v.y);
        __nv_bfloat16 h2 = __float2bfloat16(v.z), h3 = __float2bfloat16(v.w);
        ((uint2*)g_Xhi)[i] = make_uint2(pack_bf(h0, h1), pack_bf(h2, h3));
        ((uint2*)g_Xlo)[i] = make_uint2(
            pack_bf(__float2bfloat16(v.x - __bfloat162float(h0)),
                    __float2bfloat16(v.y - __bfloat162float(h1))),
            pack_bf(__float2bfloat16(v.z - __bfloat162float(h2)),
                    __float2bfloat16(v.w - __bfloat162float(h3))));
        return;
    }
    // DFT tables for the fold branches
    if (tid < 128) {
        float ang = (float)tid / 64.0f;
        cs[tid] = cospif(ang);
        sn[tid] = sinpif(ang);
    }
    __syncthreads();
    blk -= PREP_SPLIT;
    if (blk < PREP_W1) {
        // (d-outer, c-inner): consecutive lanes share d -> broadcast w loads
        int idx = blk * 256 + tid;
        int d = idx / N1P_, c = idx - d * N1P_;
        float acc = 0.f;
        if (c < N1_) {
            int region = (c >= 1040) ? 1 : 0;
            int cc = c - region * 1040;
            int hd = cc / 130;
            int u = cc - hd * 130;
            int f = u >> 1;
            const float* w = w_qkv + (size_t)d * 3072 + region * 1024 + hd * 128;
            if ((u & 1) == 0) {
                #pragma unroll 8
                for (int dd = 0; dd < 128; dd++) acc += w[dd] * cs[(f * dd) & 127];
            } else {
                #pragma unroll 8
                for (int dd = 0; dd < 128; dd++) acc -= w[dd] * sn[(f * dd) & 127];
            }
            acc *= SCALE_;
        }
        __nv_bfloat16 hi = __float2bfloat16(acc);
        g_W1T_hi[c * 128 + d] = hi;
        g_W1T_lo[c * 128 + d] = __float2bfloat16(acc - __bfloat162float(hi));
        return;
    }
    blk -= PREP_W1;
    if (blk < PREP_W1V) {
        int idx = blk * 256 + tid;
        int d = idx / NK_, k = idx - d * NK_;
        int hd = k / 130;
        int u = k - hd * 130;
        int f = u >> 1;
        const float* w = w_qkv + (size_t)d * 3072 + 2048 + hd * 128;
        float acc = 0.f;
        if ((u & 1) == 0) {
            #pragma unroll 8
            for (int dd = 0; dd < 128; dd++) acc += w[dd] * cs[(f * dd) & 127];
        } else {
            #pragma unroll 8
            for (int dd = 0; dd < 128; dd++) acc -= w[dd] * sn[(f * dd) & 127];
        }
        g_W1v[idx] = acc;
        return;
    }
    blk -= PREP_W1V;
    {
        int idx = blk * 256 + tid;     // over H_*2*F_*D_ = 133120
        int o = idx & 127;
        int r = idx >> 7;
        int x = r % 65;
        int hp = r / 65;
        int p = hp & 1, hd = hp >> 1;
        float acc = 0.f;
        if (p == 0) {
            #pragma unroll 8
            for (int t2 = 0; t2 < 128; t2++)
                acc += cs[(x * t2) & 127] * w_out[(size_t)(hd * 128 + t2) * 128 + o];
            acc *= ((x == 0 || x == 64) ? 1.0f : 2.0f) / 128.0f;
        } else if (x != 0 && x != 64) {
            #pragma unroll 8
            for (int t2 = 0; t2 < 128; t2++)
                acc -= sn[(x * t2) & 127] * w_out[(size_t)(hd * 128 + t2) * 128 + o];
            acc *= 2.0f / 128.0f;
        }
        g_Mout[idx] = acc;
    }
}

// ---------------- GEMM1: |X@W1_qk| -> aq, ak (m256 x n128, 512 thr, 2-stage) ----------------
// stage: AHI 32K @0, ALO @32768, BHI 16K @65536, BLO @81920; stride 98304
#define G1_STG 98304
__device__ __forceinline__ void g1_load(uint32_t sst, int bm, int bn, int k0, int tid) {
    #pragma unroll
    for (int u = tid; u < 2048; u += 512) {
        int r = u >> 3, cb = (u & 7) * 16;
        uint32_t d = swz64(r, cb);
        cp16(sst + d,         (const char*)g_Xhi + ((size_t)(bm + r) * 128 + k0) * 2 + cb);
        cp16(sst + 32768 + d, (const char*)g_Xlo + ((size_t)(bm + r) * 128 + k0) * 2 + cb);
    }
    #pragma unroll
    for (int u = tid; u < 1024; u += 512) {
        int r = u >> 3, cb = (u & 7) * 16;
        uint32_t d = swz64(r, cb);
        cp16(sst + 65536 + d, (const char*)g_W1T_hi + ((size_t)(bn + r) * 128 + k0) * 2 + cb);
        cp16(sst + 81920 + d, (const char*)g_W1T_lo + ((size_t)(bn + r) * 128 + k0) * 2 + cb);
    }
}

__global__ void __launch_bounds__(512, 1) gemm1_tc() {
    extern __shared__ char smem[];
    uint32_t sb = smem_u32(smem);
    int tid = threadIdx.x;
    int lane = tid & 31, wid = tid >> 5;
    int wm = wid & 7, wn = wid >> 3;      // 8 x 2 warps over 256 x 128
    int bm = blockIdx.y * 256, bn = blockIdx.x * 128;

    g1_load(sb, bm, bn, 0, tid);  cp_commit();
    g1_load(sb + G1_STG, bm, bn, 64, tid);  cp_commit();

    float c[2][8][4];
    #pragma unroll
    for (int i = 0; i < 2; i++)
        #pragma unroll
        for (int j = 0; j < 8; j++)
            #pragma unroll
            for (int k = 0; k < 4; k++) c[i][j][k] = 0.f;

    cp_wait1();
    __syncthreads();
    mma_chunk64(sb, sb + 32768, sb + 65536, sb + 81920, lane, wm, wn, c);
    cp_wait0();
    __syncthreads();
    mma_chunk64(sb + G1_STG, sb + G1_STG + 32768, sb + G1_STG + 65536,
                sb + G1_STG + 81920, lane, wm, wn, c);

    // epilogue: |q|,|k|
    int g = lane >> 2, cp2 = (lane & 3) * 2;
    #pragma unroll
    for (int tn = 0; tn < 8; tn++) {
        int col = bn + wn * 64 + tn * 8 + cp2;   // even
        if (col >= N1_) continue;
        int region = (col >= 1040) ? 1 : 0;
        int cc = col - region * 1040;
        int hd = cc / 130;
        int uu = cc - hd * 130;
        int f = uu >> 1;
        float* base = region ? g_ak : g_aq;
        #pragma unroll
        for (int tm = 0; tm < 2; tm++)
            #pragma unroll
            for (int hf = 0; hf < 2; hf++) {
                size_t row = (size_t)bm + wm * 32 + tm * 16 + hf * 8 + g;
                float re = c[tm][tn][hf * 2], im = c[tm][tn][hf * 2 + 1];
                base[(row * 8 + hd) * 65 + f] = sqrtf(re * re + im * im);
            }
    }
}

// ---------------- att partial: [f][e] transposed smem, float4 over e ----------------
__global__ void __launch_bounds__(256) att_partial_kernel() {
    __shared__ float aqs[65 * 68];
    __shared__ float aks[65 * 68];
    int bh = blockIdx.y;
    int b = bh >> 3, h = bh & 7;
    int chunk = blockIdx.x;
    int tid = threadIdx.x;
    int tx = tid & 15, ty = tid >> 4;
    int xs[5], ys[5];
    #pragma unroll
    for (int i = 0; i < 5; i++) {
        int x = tx + 16 * i; xs[i] = (x < 65) ? x : 0;
        int y = ty + 16 * i; ys[i] = (y < 65) ? y : 0;
    }
    float acc[5][5];
    #pragma unroll
    for (int i = 0; i < 5; i++)
        #pragma unroll
        for (int j = 0; j < 5; j++) acc[i][j] = 0.f;

    int ebase = chunk * (2048 / EQ_);
    for (int e0 = ebase; e0 < ebase + 2048 / EQ_; e0 += 64) {
        for (int idx = tid; idx < 4160; idx += 256) {
            int r = idx / 65, f = idx - r * 65;
            size_t gidx = ((size_t)((b * 2048 + e0 + r) * 8 + h)) * 65 + f;
            aqs[f * 68 + r] = g_aq[gidx];
            aks[f * 68 + r] = g_ak[gidx];
        }
        __syncthreads();
        #pragma unroll 2
        for (int e4 = 0; e4 < 64; e4 += 4) {
            float4 av[5], bv[5];
            #pragma unroll
            for (int i = 0; i < 5; i++) av[i] = *(const float4*)&aqs[xs[i] * 68 + e4];
            #pragma unroll
            for (int j = 0; j < 5; j++) bv[j] = *(const float4*)&aks[ys[j] * 68 + e4];
            #pragma unroll
            for (int i = 0; i < 5; i++)
                #pragma unroll
                for (int j = 0; j < 5; j++) {
                    acc[i][j] += av[i].x * bv[j].x;
                    acc[i][j] += av[i].y * bv[j].y;
                    acc[i][j] += av[i].z * bv[j].z;
                    acc[i][j] += av[i].w * bv[j].w;
                }
        }
        __syncthreads();
    }
    float* dst = g_attp + (size_t)(bh * EQ_ + chunk) * 4225;
    #pragma unroll
    for (int i = 0; i < 5; i++) {
        int x = tx + 16 * i;
        if (x < 65)
            #pragma unroll
            for (int j = 0; j < 5; j++) {
                int y = ty + 16 * j;
                if (y < 65) dst[x * 65 + y] = acc[i][j];
            }
    }
}

// ---------------- softmax ----------------
__global__ void __launch_bounds__(256) att_softmax_kernel() {
    __shared__ float sm[4225];
    int bh = blockIdx.x;
    int tid = threadIdx.x;
    const float* p0 = g_attp + (size_t)(bh * EQ_) * 4225;
    for (int idx = tid; idx < 4225; idx += 256) {
        float s = 0.f;
        #pragma unroll
        for (int q = 0; q < EQ_; q++) s += p0[q * 4225 + idx];
        sm[idx] = s;
    }
    __syncthreads();
    int warp = tid >> 5, lane = tid & 31;
    for (int x = warp; x < 65; x += 8) {
        float m = -3.4e38f;
        for (int y = lane; y < 65; y += 32) m = fmaxf(m, sm[x * 65 + y]);
        #pragma unroll
        for (int o = 16; o; o >>= 1) m = fmaxf(m, __shfl_xor_sync(0xffffffffu, m, o));
        float s = 0.f;
        for (int y = lane; y < 65; y += 32) {
            float v = expf(sm[x * 65 + y] - m);
            sm[x * 65 + y] = v;
            s += v;
        }
        #pragma unroll
        for (int o = 16; o; o >>= 1) s += __shfl_xor_sync(0xffffffffu, s, o);
        float inv = 1.0f / s;
        for (int y = lane; y < 65; y += 32)
            g_att[(size_t)bh * 4225 + x * 65 + y] = sm[x * 65 + y] * inv;
    }
}

// ---------------- build C_b ----------------
__global__ void __launch_bounds__(256) build_c_kernel() {
    extern __shared__ float csm[];
    float* att_s = csm;
    float* mout_s = csm + 4225;
    int blk = blockIdx.x;                    // b*16 + h*2 + p
    int b = blk >> 4;
    int hp = blk & 15;
    int hd = hp >> 1, p = hp & 1;
    int tid = threadIdx.x;
    int bh = b * 8 + hd;
    for (int idx = tid; idx < 4225; idx += 256)
        att_s[idx] = g_att[(size_t)bh * 4225 + idx];
    for (int idx = tid; idx < 8320; idx += 256)
        mout_s[idx] = g_Mout[(size_t)hp * 8320 + idx];
    __syncthreads();
    for (int idx = tid; idx < 8320; idx += 256) {
        int o = idx / 65, y = idx - o * 65;
        float acc = 0.f;
        #pragma unroll 5
        for (int x = 0; x < 65; x++)
            acc += att_s[x * 65 + y] * mout_s[x * 128 + o];
        int k = hd * 130 + 2 * y + p;
        g_C[((size_t)b * NK_ + k) * 128 + o] = acc;
    }
}

// ---------------- build D_b = W1v @ C_b, split to DT hi/lo ----------------
__global__ void __launch_bounds__(256) build_d_kernel() {
    __shared__ float Wvs[128 * 65];   // [d][kk]
    __shared__ float Cs[65 * 32];     // [kk][oo]
    int b = blockIdx.x;
    int o0 = blockIdx.y * 32;
    int tid = threadIdx.x;
    int ol = tid & 31, dg = tid >> 5;
    float acc[16];
    #pragma unroll
    for (int i = 0; i < 16; i++) acc[i] = 0.f;

    for (int k0 = 0; k0 < NK_; k0 += 65) {
        __syncthreads();
        for (int u = tid; u < 8320; u += 256) {
            int d = u / 65, kk = u - d * 65;
            Wvs[u] = g_W1v[(size_t)d * NK_ + k0 + kk];
        }
        for (int u = tid; u < 2080; u += 256) {
            int kk = u >> 5, oo = u & 31;
            Cs[u] = g_C[((size_t)b * NK_ + k0 + kk) * 128 + o0 + oo];
        }
        __syncthreads();
        #pragma unroll 5
        for (int kk = 0; kk < 65; kk++) {
            float cv = Cs[kk * 32 + ol];
            #pragma unroll
            for (int i = 0; i < 16; i++)
                acc[i] += Wvs[(dg + 8 * i) * 65 + kk] * cv;
        }
    }
    #pragma unroll
    for (int i = 0; i < 16; i++) {
        int d = dg + 8 * i;
        __nv_bfloat16 hi = __float2bfloat16(acc[i]);
        size_t off = ((size_t)b * 128 + o0 + ol) * 128 + d;
        g_DThi[off] = hi;
        g_DTlo[off] = __float2bfloat16(acc[i] - __bfloat162float(hi));
    }
}

// ---------------- final GEMM: out = X @ D_b + bias (m256, K=128, load-once) ----------------
#define FG_AHI 0
#define FG_ALO 65536
#define FG_BHI 131072
#define FG_BLO 163840
#define FG_TOT 196608
__global__ void __launch_bounds__(512, 1) final_gemm(float* __restrict__ out,
                                                     const float* __restrict__ bias) {
    extern __shared__ char smem[];
    uint32_t sb = smem_u32(smem);
    int tid = threadIdx.x;
    int lane = tid & 31, wid = tid >> 5;
    int wm = wid & 7, wn = wid >> 3;
    int bm = blockIdx.x * 256;
    int b = bm >> 11;

    #pragma unroll
    for (int u = tid; u < 4096; u += 512) {
        int r = u >> 4, seg = u & 15;
        int ch = seg >> 3, cb = (seg & 7) * 16;
        uint32_t d = ch * 32768 + swz64(r, cb);
        size_t src = (size_t)(bm + r) * 256 + ch * 128 + cb;
        cp16(sb + FG_AHI + d, (const char*)g_Xhi + src);
        cp16(sb + FG_ALO + d, (const char*)g_Xlo + src);
    }
    #pragma unroll
    for (int u = tid; u < 2048; u += 512) {
        int r = u >> 4, seg = u & 15;
        int ch = seg >> 3, cb = (seg & 7) * 16;
        uint32_t d = ch * 16384 + swz64(r, cb);
        size_t src = ((size_t)(b * 128 + r)) * 256 + ch * 128 + cb;
        cp16(sb + FG_BHI + d, (const char*)g_DThi + src);
        cp16(sb + FG_BLO + d, (const char*)g_DTlo + src);
    }
    cp_commit();
    cp_wait0();
    __syncthreads();

    float c[2][8][4];
    #pragma unroll
    for (int i = 0; i < 2; i++)
        #pragma unroll
        for (int j = 0; j < 8; j++)
            #pragma unroll
            for (int k = 0; k < 4; k++) c[i][j][k] = 0.f;

    #pragma unroll
    for (int ch = 0; ch < 2; ch++)
        mma_chunk64(sb + FG_AHI + ch * 32768, sb + FG_ALO + ch * 32768,
                    sb + FG_BHI + ch * 16384, sb + FG_BLO + ch * 16384,
                    lane, wm, wn, c);

    int g = lane >> 2, cp2 = (lane & 3) * 2;
    #pragma unroll
    for (int tm = 0; tm < 2; tm++)
        #pragma unroll
        for (int hf = 0; hf < 2; hf++) {
            size_t row = (size_t)bm + wm * 32 + tm * 16 + hf * 8 + g;
            float* dst = out + row * 128;
            #pragma unroll
            for (int tn = 0; tn < 8; tn++) {
                int col = wn * 64 + tn * 8 + cp2;
                float2 bv = *(const float2*)(bias + col);
                *(float2*)(dst + col) = make_float2(c[tm][tn][hf * 2] + bv.x,
                                                    c[tm][tn][hf * 2 + 1] + bv.y);
            }
        }
}

// ---------------- launch ----------------
extern "C" void kernel_launch(void* const* d_in, const int* in_sizes, int n_in,
                              void* d_out, int out_size) {
    const float* x     = (const float*)d_in[0];
    const float* w_qkv = (const float*)d_in[1];
    const float* w_out = (const float*)d_in[2];
    const float* b_out = (const float*)d_in[3];
    float* out = (float*)d_out;

    cudaFuncSetAttribute(gemm1_tc, cudaFuncAttributeMaxDynamicSharedMemorySize, 2 * G1_STG);
    cudaFuncSetAttribute(final_gemm, cudaFuncAttributeMaxDynamicSharedMemorySize, FG_TOT);
    cudaFuncSetAttribute(build_c_kernel, cudaFuncAttributeMaxDynamicSharedMemorySize,
                         (4225 + 8320) * 4);

    prep_kernel<<<PREP_TOTAL, 256>>>(x, w_qkv, w_out);
    gemm1_tc<<<dim3(N1P_ / 128, ROWS_ / 256), 512, 2 * G1_STG>>>();
    att_partial_kernel<<<dim3(EQ_, B_ * H_), 256>>>();
    att_softmax_kernel<<<B_ * H_, 256>>>();
    build_c_kernel<<<B_ * H_ * 2, 256, (4225 + 8320) * 4>>>();
    build_d_kernel<<<dim3(B_, 4), 256>>>();
    final_gemm<<<ROWS_ / 256, 512, FG_TOT>>>(out, b_out);
}